// round 10
// baseline (speedup 1.0000x reference)
#include <cuda_runtime.h>
#include <math.h>

#define N   8192
#define NZ  256
#define NC  128
#define DT_ 0.1f

// k_rz: z = W_rz @ r, 8-way column split, 4 rows per block -> 512 blocks
#define SPL_A 8
#define CHA4  (N / 4 / SPL_A)          // 256 float4 per column chunk

// k_big: persistent grid-stride over rows
#define BGRID 1024                     // 8192 / 1024 = 8 rows per block

// Scratch (__device__ globals)
__device__ float g_r[N];
__device__ float g_zpart[SPL_A][NZ];
__device__ float g_rn[N];

// Fast tanh: 1 - 2/(exp(2x)+1). MUFU.EX2 + MUFU.RCP path, no branches.
__inline__ __device__ float ftanh(float x) {
    float e = __expf(2.0f * x);
    return 1.0f - __fdividef(2.0f, e + 1.0f);
}

__inline__ __device__ float dot4(float4 a, float4 b) {
    return a.x * b.x + a.y * b.y + a.z * b.z + a.w * b.w;
}

// Block reduce, up to 16 warps. Valid in thread 0. Safe for reuse in a loop
// (trailing barrier protects the smem buffer).
__inline__ __device__ float block_reduce_w(float v, int nwarps) {
    __shared__ float sm[16];
    const int lane = threadIdx.x & 31;
    const int wid  = threadIdx.x >> 5;
    #pragma unroll
    for (int o = 16; o; o >>= 1) v += __shfl_down_sync(0xffffffffu, v, o);
    if (lane == 0) sm[wid] = v;
    __syncthreads();
    if (wid == 0) {
        v = (lane < nwarps) ? sm[lane] : 0.f;
        #pragma unroll
        for (int o = 8; o; o >>= 1) v += __shfl_down_sync(0xffffffffu, v, o);
    }
    __syncthreads();
    return v;
}

// 4-wide block reduce, 8 warps (256 threads). Valid in thread 0.
__inline__ __device__ float4 block_reduce4(float4 v) {
    __shared__ float4 sm4[8];
    const int lane = threadIdx.x & 31;
    const int wid  = threadIdx.x >> 5;
    #pragma unroll
    for (int o = 16; o; o >>= 1) {
        v.x += __shfl_down_sync(0xffffffffu, v.x, o);
        v.y += __shfl_down_sync(0xffffffffu, v.y, o);
        v.z += __shfl_down_sync(0xffffffffu, v.z, o);
        v.w += __shfl_down_sync(0xffffffffu, v.w, o);
    }
    if (lane == 0) sm4[wid] = v;
    __syncthreads();
    if (wid == 0) {
        v = (lane < 8) ? sm4[lane] : make_float4(0.f, 0.f, 0.f, 0.f);
        #pragma unroll
        for (int o = 4; o; o >>= 1) {
            v.x += __shfl_down_sync(0xffffffffu, v.x, o);
            v.y += __shfl_down_sync(0xffffffffu, v.y, o);
            v.z += __shfl_down_sync(0xffffffffu, v.z, o);
            v.w += __shfl_down_sync(0xffffffffu, v.w, o);
        }
    }
    return v;
}

// ---------------------------------------------------------------------------
// Kernel 1: r = tanh(x+b) for split-owned chunks (row-group 0 persists g_r)
// + split-K partials of z = W_rz @ r for 4 rows/block.
// Grid: 64 row-groups * 8 splits = 512 blocks, 256 threads (1 float4/thread).
// ---------------------------------------------------------------------------
__global__ void __launch_bounds__(256) k_rz(
    const float* __restrict__ x, const float* __restrict__ b,
    const float* __restrict__ W_rz)
{
    const int s    = blockIdx.x & (SPL_A - 1);
    const int rg   = blockIdx.x >> 3;
    const int row0 = rg * 4;
    const int c4   = s * CHA4 + threadIdx.x;

    float4 xv = ((const float4*)x)[c4];
    float4 bv = ((const float4*)b)[c4];

    const float4* w0 = (const float4*)(W_rz + (size_t)(row0 + 0) * N);
    const float4* w1 = (const float4*)(W_rz + (size_t)(row0 + 1) * N);
    const float4* w2 = (const float4*)(W_rz + (size_t)(row0 + 2) * N);
    const float4* w3 = (const float4*)(W_rz + (size_t)(row0 + 3) * N);
    float4 a0 = __ldcs(&w0[c4]);
    float4 a1 = __ldcs(&w1[c4]);
    float4 a2 = __ldcs(&w2[c4]);
    float4 a3 = __ldcs(&w3[c4]);

    float4 r0;
    r0.x = ftanh(xv.x + bv.x); r0.y = ftanh(xv.y + bv.y);
    r0.z = ftanh(xv.z + bv.z); r0.w = ftanh(xv.w + bv.w);
    if (rg == 0) ((float4*)g_r)[c4] = r0;

    float4 acc = make_float4(dot4(a0, r0), dot4(a1, r0),
                             dot4(a2, r0), dot4(a3, r0));
    acc = block_reduce4(acc);
    if (threadIdx.x == 0) {
        g_zpart[s][row0 + 0] = acc.x;
        g_zpart[s][row0 + 1] = acc.y;
        g_zpart[s][row0 + 2] = acc.z;
        g_zpart[s][row0 + 3] = acc.w;
    }
}

// ---------------------------------------------------------------------------
// Kernel 2: fused row update — persistent grid-stride version.
// Grid: 1024 blocks x 256 threads; each block handles rows bid, bid+1024, ...
// (8 rows). Single wave: no wave-tail raggedness, no per-wave latency ramp.
// g_r reads are L1-hot after the first row.
// ---------------------------------------------------------------------------
__global__ void __launch_bounds__(256) k_big(
    const float* __restrict__ W_rr, const float* __restrict__ W_zr,
    const float* __restrict__ W_cr, const float* __restrict__ W_epsr,
    const float* __restrict__ x,    const float* __restrict__ eps,
    const float* __restrict__ c,    const float* __restrict__ b,
    float* __restrict__ out)
{
    const int t = threadIdx.x;
    const float4* __restrict__ v = (const float4*)g_r;

    // Hoist the z sum (fixed split order) out of the row loop: threads 64..127
    // keep their float4 of z in registers across all 8 rows.
    float4 zq = make_float4(0.f, 0.f, 0.f, 0.f);
    float4 sidev = make_float4(0.f, 0.f, 0.f, 0.f);
    if (t < 64) {
        sidev = ((const float4*)eps)[t];
    } else if (t < 128) {
        const int k = t - 64;
        zq = ((const float4*)g_zpart[0])[k];
        #pragma unroll
        for (int s = 1; s < SPL_A; s++) {
            float4 p = ((const float4*)g_zpart[s])[k];
            zq.x += p.x; zq.y += p.y; zq.z += p.z; zq.w += p.w;
        }
        sidev = zq;
    } else if (t < 160) {
        sidev = ((const float4*)c)[t - 128];
    }

    for (int row = blockIdx.x; row < N; row += BGRID) {
        const float4* __restrict__ w = (const float4*)(W_rr + (size_t)row * N);

        // Front-batch all 8 weight loads (independent DRAM streams)
        float4 wv[8];
        #pragma unroll
        for (int i = 0; i < 8; i++) wv[i] = __ldcs(&w[t + i * 256]);

        float a0 = 0.f, a1 = 0.f, a2 = 0.f, a3 = 0.f;
        #pragma unroll
        for (int i = 0; i < 8; i++) {
            float d = dot4(wv[i], v[t + i * 256]);
            if ((i & 3) == 0) a0 += d;
            else if ((i & 3) == 1) a1 += d;
            else if ((i & 3) == 2) a2 += d;
            else a3 += d;
        }
        float acc = (a0 + a1) + (a2 + a3);

        // Side dots on disjoint thread ranges (side vectors in registers)
        if (t < 64) {
            float4 a = __ldcs(((const float4*)(W_epsr + (size_t)row * NZ)) + t);
            acc += dot4(a, sidev);
        } else if (t < 128) {
            float4 a = __ldcs(((const float4*)(W_zr + (size_t)row * NZ)) + (t - 64));
            acc += dot4(a, sidev);
        } else if (t < 160) {
            float4 a = __ldcs(((const float4*)(W_cr + (size_t)row * NC)) + (t - 128));
            acc += dot4(a, sidev);
        }

        acc = block_reduce_w(acc, 8);
        if (t == 0) {
            float xv = x[row];
            float xn = xv + DT_ * (acc - xv);
            out[row] = xn;
            float rn = ftanh(xn + b[row]);
            out[N + row] = rn;
            g_rn[row] = rn;
        }
    }
}

// ---------------------------------------------------------------------------
// Kernel 3: z_new / c_new / eps_new. One block per output row, 512 threads,
// 4 contiguous float4 each, front-batched. No atomics, no fences.
// ---------------------------------------------------------------------------
__global__ void __launch_bounds__(512) k_tail(
    const float* __restrict__ W_rz, const float* __restrict__ W_rc,
    const float* __restrict__ z_tilde, float* __restrict__ out)
{
    const int idx = blockIdx.x;     // 0..383
    const float* __restrict__ Wrow = (idx < NZ)
        ? (W_rz + (size_t)idx * N)
        : (W_rc + (size_t)(idx - NZ) * N);
    const float4* __restrict__ w = (const float4*)Wrow;
    const float4* __restrict__ v = (const float4*)g_rn;
    const int base = threadIdx.x * 4;

    float4 w0 = __ldcs(&w[base + 0]), w1 = __ldcs(&w[base + 1]);
    float4 w2 = __ldcs(&w[base + 2]), w3 = __ldcs(&w[base + 3]);
    float4 v0 = v[base + 0], v1 = v[base + 1];
    float4 v2 = v[base + 2], v3 = v[base + 3];

    float acc = (dot4(w0, v0) + dot4(w1, v1)) + (dot4(w2, v2) + dot4(w3, v3));
    acc = block_reduce_w(acc, 16);
    if (threadIdx.x == 0) {
        if (idx < NZ) {
            out[2 * N + idx] = acc;                          // z_new
            out[2 * N + NZ + NC + idx] = acc - z_tilde[idx]; // eps_new
        } else {
            out[2 * N + NZ + (idx - NZ)] = acc;              // c_new
        }
    }
}

extern "C" void kernel_launch(void* const* d_in, const int* in_sizes, int n_in,
                              void* d_out, int out_size) {
    // metadata order: x, eps, c, z_tilde, W_rr, W_zr, W_cr, W_epsr, W_rz, W_rc, b
    const float* x       = (const float*)d_in[0];
    const float* eps     = (const float*)d_in[1];
    const float* c       = (const float*)d_in[2];
    const float* z_tilde = (const float*)d_in[3];
    const float* W_rr    = (const float*)d_in[4];
    const float* W_zr    = (const float*)d_in[5];
    const float* W_cr    = (const float*)d_in[6];
    const float* W_epsr  = (const float*)d_in[7];
    const float* W_rz    = (const float*)d_in[8];
    const float* W_rc    = (const float*)d_in[9];
    const float* b       = (const float*)d_in[10];
    float* out = (float*)d_out;

    k_rz  <<<(NZ / 4) * SPL_A, 256>>>(x, b, W_rz);
    k_big <<<BGRID, 256>>>(W_rr, W_zr, W_cr, W_epsr, x, eps, c, b, out);
    k_tail<<<NZ + NC, 512>>>(W_rz, W_rc, z_tilde, out);
}

// round 12
// speedup vs baseline: 1.0148x; 1.0148x over previous
#include <cuda_runtime.h>
#include <math.h>

#define N   8192
#define NZ  256
#define NC  128
#define DT_ 0.1f

// k_rz: z = W_rz @ r, 8-way column split, 4 rows per block -> 512 blocks
#define SPL_A 8
#define CHA4  (N / 4 / SPL_A)          // 256 float4 per column chunk

// Scratch (__device__ globals; zero-initialized at module load)
__device__ float g_r[N];
__device__ float g_zpart[SPL_A][NZ];
__device__ float g_rn[N];
__device__ int   g_done;               // k_big row completions
__device__ int   g_done2;              // tail block completions (for reset)

// Fast tanh: 1 - 2/(exp(2x)+1). MUFU.EX2 + MUFU.RCP path, no branches.
__inline__ __device__ float ftanh(float x) {
    float e = __expf(2.0f * x);
    return 1.0f - __fdividef(2.0f, e + 1.0f);
}

__inline__ __device__ float dot4(float4 a, float4 b) {
    return a.x * b.x + a.y * b.y + a.z * b.z + a.w * b.w;
}

// Block reduce, up to 16 warps. Valid in thread 0.
__inline__ __device__ float block_reduce_w(float v, int nwarps) {
    __shared__ float sm[16];
    const int lane = threadIdx.x & 31;
    const int wid  = threadIdx.x >> 5;
    #pragma unroll
    for (int o = 16; o; o >>= 1) v += __shfl_down_sync(0xffffffffu, v, o);
    if (lane == 0) sm[wid] = v;
    __syncthreads();
    if (wid == 0) {
        v = (lane < nwarps) ? sm[lane] : 0.f;
        #pragma unroll
        for (int o = 8; o; o >>= 1) v += __shfl_down_sync(0xffffffffu, v, o);
    }
    return v;
}

// 4-wide block reduce, 8 warps (256 threads). Valid in thread 0.
__inline__ __device__ float4 block_reduce4(float4 v) {
    __shared__ float4 sm4[8];
    const int lane = threadIdx.x & 31;
    const int wid  = threadIdx.x >> 5;
    #pragma unroll
    for (int o = 16; o; o >>= 1) {
        v.x += __shfl_down_sync(0xffffffffu, v.x, o);
        v.y += __shfl_down_sync(0xffffffffu, v.y, o);
        v.z += __shfl_down_sync(0xffffffffu, v.z, o);
        v.w += __shfl_down_sync(0xffffffffu, v.w, o);
    }
    if (lane == 0) sm4[wid] = v;
    __syncthreads();
    if (wid == 0) {
        v = (lane < 8) ? sm4[lane] : make_float4(0.f, 0.f, 0.f, 0.f);
        #pragma unroll
        for (int o = 4; o; o >>= 1) {
            v.x += __shfl_down_sync(0xffffffffu, v.x, o);
            v.y += __shfl_down_sync(0xffffffffu, v.y, o);
            v.z += __shfl_down_sync(0xffffffffu, v.z, o);
            v.w += __shfl_down_sync(0xffffffffu, v.w, o);
        }
    }
    return v;
}

// ---------------------------------------------------------------------------
// Kernel 1: r = tanh(x+b) for split-owned chunks (row-group 0 persists g_r)
// + split-K partials of z = W_rz @ r for 4 rows/block.
// Grid: 64 row-groups * 8 splits = 512 blocks, 256 threads (1 float4/thread).
// ---------------------------------------------------------------------------
__global__ void __launch_bounds__(256) k_rz(
    const float* __restrict__ x, const float* __restrict__ b,
    const float* __restrict__ W_rz)
{
    const int s    = blockIdx.x & (SPL_A - 1);
    const int rg   = blockIdx.x >> 3;
    const int row0 = rg * 4;
    const int c4   = s * CHA4 + threadIdx.x;

    float4 xv = ((const float4*)x)[c4];
    float4 bv = ((const float4*)b)[c4];

    const float4* w0 = (const float4*)(W_rz + (size_t)(row0 + 0) * N);
    const float4* w1 = (const float4*)(W_rz + (size_t)(row0 + 1) * N);
    const float4* w2 = (const float4*)(W_rz + (size_t)(row0 + 2) * N);
    const float4* w3 = (const float4*)(W_rz + (size_t)(row0 + 3) * N);
    float4 a0 = __ldcs(&w0[c4]);
    float4 a1 = __ldcs(&w1[c4]);
    float4 a2 = __ldcs(&w2[c4]);
    float4 a3 = __ldcs(&w3[c4]);

    float4 r0;
    r0.x = ftanh(xv.x + bv.x); r0.y = ftanh(xv.y + bv.y);
    r0.z = ftanh(xv.z + bv.z); r0.w = ftanh(xv.w + bv.w);
    if (rg == 0) ((float4*)g_r)[c4] = r0;

    float4 acc = make_float4(dot4(a0, r0), dot4(a1, r0),
                             dot4(a2, r0), dot4(a3, r0));
    acc = block_reduce4(acc);
    if (threadIdx.x == 0) {
        g_zpart[s][row0 + 0] = acc.x;
        g_zpart[s][row0 + 1] = acc.y;
        g_zpart[s][row0 + 2] = acc.z;
        g_zpart[s][row0 + 3] = acc.w;
    }
}

// ---------------------------------------------------------------------------
// Kernel 2 (merged): R9 one-row-per-block k_big PLUS trailing tail blocks.
//  Blocks [0, N):       row update (x_new, r_new); signal g_done.
//  Blocks [N, N+384):   issued after all k_big blocks (bid order). Spin
//                       (with nanosleep back-off) for g_done==N, then compute
//                       one z_new/c_new/eps_new row.
// Grid: N + 384 blocks, 256 threads.
// ---------------------------------------------------------------------------
__global__ void __launch_bounds__(256) k_big(
    const float* __restrict__ W_rr, const float* __restrict__ W_zr,
    const float* __restrict__ W_cr, const float* __restrict__ W_epsr,
    const float* __restrict__ W_rz, const float* __restrict__ W_rc,
    const float* __restrict__ x,    const float* __restrict__ eps,
    const float* __restrict__ c,    const float* __restrict__ b,
    const float* __restrict__ z_tilde,
    float* __restrict__ out)
{
    const int t = threadIdx.x;

    if (blockIdx.x < N) {
        // ---- row update (exact R9 structure) ----
        const int row = blockIdx.x;
        const float4* __restrict__ w = (const float4*)(W_rr + (size_t)row * N);
        const float4* __restrict__ v = (const float4*)g_r;

        // Front-batch all 8 weight loads (independent DRAM streams)
        float4 wv[8];
        #pragma unroll
        for (int i = 0; i < 8; i++) wv[i] = __ldcs(&w[t + i * 256]);

        float a0 = 0.f, a1 = 0.f, a2 = 0.f, a3 = 0.f;
        #pragma unroll
        for (int i = 0; i < 8; i++) {
            float d = dot4(wv[i], v[t + i * 256]);   // v: L1-hit after first block
            if ((i & 3) == 0) a0 += d;
            else if ((i & 3) == 1) a1 += d;
            else if ((i & 3) == 2) a2 += d;
            else a3 += d;
        }
        float acc = (a0 + a1) + (a2 + a3);

        // Side dots on disjoint thread ranges (640 extra elems per row)
        if (t < 64) {                               // W_epsr row · eps
            float4 a = __ldcs(((const float4*)(W_epsr + (size_t)row * NZ)) + t);
            acc += dot4(a, ((const float4*)eps)[t]);
        } else if (t < 128) {                       // W_zr row · z (fixed split order)
            const int k = t - 64;
            float4 a = __ldcs(((const float4*)(W_zr + (size_t)row * NZ)) + k);
            float4 q = ((const float4*)g_zpart[0])[k];
            #pragma unroll
            for (int s = 1; s < SPL_A; s++) {
                float4 p = ((const float4*)g_zpart[s])[k];
                q.x += p.x; q.y += p.y; q.z += p.z; q.w += p.w;
            }
            acc += dot4(a, q);
        } else if (t < 160) {                       // W_cr row · c
            const int k = t - 128;
            float4 a = __ldcs(((const float4*)(W_cr + (size_t)row * NC)) + k);
            acc += dot4(a, ((const float4*)c)[k]);
        }

        acc = block_reduce_w(acc, 8);
        if (t == 0) {
            float xv = x[row];
            float xn = xv + DT_ * (acc - xv);
            out[row] = xn;
            float rn = ftanh(xn + b[row]);
            out[N + row] = rn;
            g_rn[row] = rn;
            __threadfence();
            atomicAdd(&g_done, 1);
        }
        return;
    }

    // ---- tail block: one z_new/c_new row against r_new ----
    const int idx = blockIdx.x - N;   // 0..383
    if (t == 0) {
        while (*(volatile int*)&g_done < N) { __nanosleep(64); }
        __threadfence();              // acquire: g_rn writes visible
    }
    __syncthreads();

    const float* __restrict__ Wrow = (idx < NZ)
        ? (W_rz + (size_t)idx * N)
        : (W_rc + (size_t)(idx - NZ) * N);
    const float4* __restrict__ w = (const float4*)Wrow;
    const float4* __restrict__ v = (const float4*)g_rn;
    const int base = t * 8;

    // Front-batch 8 weight loads + 8 vector loads
    float4 wv[8];
    #pragma unroll
    for (int i = 0; i < 8; i++) wv[i] = __ldcs(&w[base + i]);
    float acc = 0.f;
    #pragma unroll
    for (int i = 0; i < 8; i++) acc += dot4(wv[i], __ldcg(&v[base + i]));

    acc = block_reduce_w(acc, 8);
    if (t == 0) {
        if (idx < NZ) {
            out[2 * N + idx] = acc;                          // z_new
            out[2 * N + NZ + NC + idx] = acc - z_tilde[idx]; // eps_new
        } else {
            out[2 * N + NZ + (idx - NZ)] = acc;              // c_new
        }
        // Reset counters for next graph replay (last tail block; by then all
        // tail blocks have passed their spin and finished their stores).
        int old = atomicAdd(&g_done2, 1);
        if (old == (NZ + NC) - 1) {
            g_done  = 0;
            g_done2 = 0;
        }
    }
}

extern "C" void kernel_launch(void* const* d_in, const int* in_sizes, int n_in,
                              void* d_out, int out_size) {
    // metadata order: x, eps, c, z_tilde, W_rr, W_zr, W_cr, W_epsr, W_rz, W_rc, b
    const float* x       = (const float*)d_in[0];
    const float* eps     = (const float*)d_in[1];
    const float* c       = (const float*)d_in[2];
    const float* z_tilde = (const float*)d_in[3];
    const float* W_rr    = (const float*)d_in[4];
    const float* W_zr    = (const float*)d_in[5];
    const float* W_cr    = (const float*)d_in[6];
    const float* W_epsr  = (const float*)d_in[7];
    const float* W_rz    = (const float*)d_in[8];
    const float* W_rc    = (const float*)d_in[9];
    const float* b       = (const float*)d_in[10];
    float* out = (float*)d_out;

    k_rz <<<(NZ / 4) * SPL_A, 256>>>(x, b, W_rz);
    k_big<<<N + NZ + NC, 256>>>(W_rr, W_zr, W_cr, W_epsr, W_rz, W_rc,
                                x, eps, c, b, z_tilde, out);
}

// round 13
// speedup vs baseline: 1.2794x; 1.2608x over previous
#include <cuda_runtime.h>
#include <math.h>

#define N   8192
#define NZ  256
#define NC  128
#define DT_ 0.1f

// k_rz: z = W_rz @ r, 8-way column split, 4 rows per block -> 512 blocks
#define SPL_A 8
#define CHA4  (N / 4 / SPL_A)          // 256 float4 per column chunk

// Scratch (__device__ globals)
__device__ float g_r[N];
__device__ float g_zpart[SPL_A][NZ];
__device__ float g_rn[N];

// Fast tanh: 1 - 2/(exp(2x)+1). MUFU.EX2 + MUFU.RCP path, no branches.
__inline__ __device__ float ftanh(float x) {
    float e = __expf(2.0f * x);
    return 1.0f - __fdividef(2.0f, e + 1.0f);
}

__inline__ __device__ float dot4(float4 a, float4 b) {
    return a.x * b.x + a.y * b.y + a.z * b.z + a.w * b.w;
}

// 256-bit global load (sm_100+: LDG.E.256). Returns 8 floats.
struct F8 { float f0, f1, f2, f3, f4, f5, f6, f7; };
__inline__ __device__ F8 ldg256(const float* p) {
    unsigned r0, r1, r2, r3, r4, r5, r6, r7;
    asm volatile("ld.global.v8.b32 {%0,%1,%2,%3,%4,%5,%6,%7}, [%8];"
                 : "=r"(r0), "=r"(r1), "=r"(r2), "=r"(r3),
                   "=r"(r4), "=r"(r5), "=r"(r6), "=r"(r7)
                 : "l"(p));
    F8 o;
    o.f0 = __uint_as_float(r0); o.f1 = __uint_as_float(r1);
    o.f2 = __uint_as_float(r2); o.f3 = __uint_as_float(r3);
    o.f4 = __uint_as_float(r4); o.f5 = __uint_as_float(r5);
    o.f6 = __uint_as_float(r6); o.f7 = __uint_as_float(r7);
    return o;
}

// Block reduce, up to 16 warps. Valid in thread 0.
__inline__ __device__ float block_reduce_w(float v, int nwarps) {
    __shared__ float sm[16];
    const int lane = threadIdx.x & 31;
    const int wid  = threadIdx.x >> 5;
    #pragma unroll
    for (int o = 16; o; o >>= 1) v += __shfl_down_sync(0xffffffffu, v, o);
    if (lane == 0) sm[wid] = v;
    __syncthreads();
    if (wid == 0) {
        v = (lane < nwarps) ? sm[lane] : 0.f;
        #pragma unroll
        for (int o = 8; o; o >>= 1) v += __shfl_down_sync(0xffffffffu, v, o);
    }
    return v;
}

// 4-wide block reduce, 8 warps (256 threads). Valid in thread 0.
__inline__ __device__ float4 block_reduce4(float4 v) {
    __shared__ float4 sm4[8];
    const int lane = threadIdx.x & 31;
    const int wid  = threadIdx.x >> 5;
    #pragma unroll
    for (int o = 16; o; o >>= 1) {
        v.x += __shfl_down_sync(0xffffffffu, v.x, o);
        v.y += __shfl_down_sync(0xffffffffu, v.y, o);
        v.z += __shfl_down_sync(0xffffffffu, v.z, o);
        v.w += __shfl_down_sync(0xffffffffu, v.w, o);
    }
    if (lane == 0) sm4[wid] = v;
    __syncthreads();
    if (wid == 0) {
        v = (lane < 8) ? sm4[lane] : make_float4(0.f, 0.f, 0.f, 0.f);
        #pragma unroll
        for (int o = 4; o; o >>= 1) {
            v.x += __shfl_down_sync(0xffffffffu, v.x, o);
            v.y += __shfl_down_sync(0xffffffffu, v.y, o);
            v.z += __shfl_down_sync(0xffffffffu, v.z, o);
            v.w += __shfl_down_sync(0xffffffffu, v.w, o);
        }
    }
    return v;
}

// ---------------------------------------------------------------------------
// Kernel 1: r = tanh(x+b) for split-owned chunks (row-group 0 persists g_r)
// + split-K partials of z = W_rz @ r for 4 rows/block.
// Grid: 64 row-groups * 8 splits = 512 blocks, 256 threads (1 float4/thread).
// ---------------------------------------------------------------------------
__global__ void __launch_bounds__(256) k_rz(
    const float* __restrict__ x, const float* __restrict__ b,
    const float* __restrict__ W_rz)
{
    const int s    = blockIdx.x & (SPL_A - 1);
    const int rg   = blockIdx.x >> 3;
    const int row0 = rg * 4;
    const int c4   = s * CHA4 + threadIdx.x;

    float4 xv = ((const float4*)x)[c4];
    float4 bv = ((const float4*)b)[c4];

    const float4* w0 = (const float4*)(W_rz + (size_t)(row0 + 0) * N);
    const float4* w1 = (const float4*)(W_rz + (size_t)(row0 + 1) * N);
    const float4* w2 = (const float4*)(W_rz + (size_t)(row0 + 2) * N);
    const float4* w3 = (const float4*)(W_rz + (size_t)(row0 + 3) * N);
    float4 a0 = __ldcs(&w0[c4]);
    float4 a1 = __ldcs(&w1[c4]);
    float4 a2 = __ldcs(&w2[c4]);
    float4 a3 = __ldcs(&w3[c4]);

    float4 r0;
    r0.x = ftanh(xv.x + bv.x); r0.y = ftanh(xv.y + bv.y);
    r0.z = ftanh(xv.z + bv.z); r0.w = ftanh(xv.w + bv.w);
    if (rg == 0) ((float4*)g_r)[c4] = r0;

    float4 acc = make_float4(dot4(a0, r0), dot4(a1, r0),
                             dot4(a2, r0), dot4(a3, r0));
    acc = block_reduce4(acc);
    if (threadIdx.x == 0) {
        g_zpart[s][row0 + 0] = acc.x;
        g_zpart[s][row0 + 1] = acc.y;
        g_zpart[s][row0 + 2] = acc.z;
        g_zpart[s][row0 + 3] = acc.w;
    }
}

// ---------------------------------------------------------------------------
// Kernel 2: fused row update, one row per block (R9 structure), weight row
// read with 4x LDG.256 (front-batched) instead of 8x LDG.128.
// Grid: 8192 blocks, 256 threads.
// ---------------------------------------------------------------------------
__global__ void __launch_bounds__(256) k_big(
    const float* __restrict__ W_rr, const float* __restrict__ W_zr,
    const float* __restrict__ W_cr, const float* __restrict__ W_epsr,
    const float* __restrict__ x,    const float* __restrict__ eps,
    const float* __restrict__ c,    const float* __restrict__ b,
    float* __restrict__ out)
{
    const int row = blockIdx.x;
    const int t   = threadIdx.x;

    const float* __restrict__ wrow = W_rr + (size_t)row * N;
    const float4* __restrict__ v = (const float4*)g_r;

    // Front-batch 4x 256-bit weight loads (independent DRAM streams).
    // Thread t covers float8 positions t, t+256, t+512, t+768.
    F8 wv[4];
    #pragma unroll
    for (int i = 0; i < 4; i++) wv[i] = ldg256(wrow + (size_t)(t + i * 256) * 8);

    float a0 = 0.f, a1 = 0.f, a2 = 0.f, a3 = 0.f;
    #pragma unroll
    for (int i = 0; i < 4; i++) {
        // r float4 indices for this float8: 2*(t+i*256), +1  (L1-hit after blk 0)
        const int k = 2 * (t + i * 256);
        float4 r0 = v[k], r1 = v[k + 1];
        a0 += wv[i].f0 * r0.x + wv[i].f1 * r0.y;
        a1 += wv[i].f2 * r0.z + wv[i].f3 * r0.w;
        a2 += wv[i].f4 * r1.x + wv[i].f5 * r1.y;
        a3 += wv[i].f6 * r1.z + wv[i].f7 * r1.w;
    }
    float acc = (a0 + a1) + (a2 + a3);

    // Side dots on disjoint thread ranges (640 extra elems per row)
    if (t < 64) {                               // W_epsr row · eps
        float4 a = __ldcs(((const float4*)(W_epsr + (size_t)row * NZ)) + t);
        acc += dot4(a, ((const float4*)eps)[t]);
    } else if (t < 128) {                       // W_zr row · z (fixed split order)
        const int k = t - 64;
        float4 a = __ldcs(((const float4*)(W_zr + (size_t)row * NZ)) + k);
        float4 q = ((const float4*)g_zpart[0])[k];
        #pragma unroll
        for (int s = 1; s < SPL_A; s++) {
            float4 p = ((const float4*)g_zpart[s])[k];
            q.x += p.x; q.y += p.y; q.z += p.z; q.w += p.w;
        }
        acc += dot4(a, q);
    } else if (t < 160) {                       // W_cr row · c
        const int k = t - 128;
        float4 a = __ldcs(((const float4*)(W_cr + (size_t)row * NC)) + k);
        acc += dot4(a, ((const float4*)c)[k]);
    }

    acc = block_reduce_w(acc, 8);
    if (t == 0) {
        float xv = x[row];
        float xn = xv + DT_ * (acc - xv);
        out[row] = xn;
        float rn = ftanh(xn + b[row]);
        out[N + row] = rn;
        g_rn[row] = rn;
    }
}

// ---------------------------------------------------------------------------
// Kernel 3: z_new / c_new / eps_new. One block per output row, 512 threads,
// 4 contiguous float4 each, front-batched. No atomics, no fences.
// ---------------------------------------------------------------------------
__global__ void __launch_bounds__(512) k_tail(
    const float* __restrict__ W_rz, const float* __restrict__ W_rc,
    const float* __restrict__ z_tilde, float* __restrict__ out)
{
    const int idx = blockIdx.x;     // 0..383
    const float* __restrict__ Wrow = (idx < NZ)
        ? (W_rz + (size_t)idx * N)
        : (W_rc + (size_t)(idx - NZ) * N);
    const float4* __restrict__ w = (const float4*)Wrow;
    const float4* __restrict__ v = (const float4*)g_rn;
    const int base = threadIdx.x * 4;

    float4 w0 = __ldcs(&w[base + 0]), w1 = __ldcs(&w[base + 1]);
    float4 w2 = __ldcs(&w[base + 2]), w3 = __ldcs(&w[base + 3]);
    float4 v0 = v[base + 0], v1 = v[base + 1];
    float4 v2 = v[base + 2], v3 = v[base + 3];

    float acc = (dot4(w0, v0) + dot4(w1, v1)) + (dot4(w2, v2) + dot4(w3, v3));
    acc = block_reduce_w(acc, 16);
    if (threadIdx.x == 0) {
        if (idx < NZ) {
            out[2 * N + idx] = acc;                          // z_new
            out[2 * N + NZ + NC + idx] = acc - z_tilde[idx]; // eps_new
        } else {
            out[2 * N + NZ + (idx - NZ)] = acc;              // c_new
        }
    }
}

extern "C" void kernel_launch(void* const* d_in, const int* in_sizes, int n_in,
                              void* d_out, int out_size) {
    // metadata order: x, eps, c, z_tilde, W_rr, W_zr, W_cr, W_epsr, W_rz, W_rc, b
    const float* x       = (const float*)d_in[0];
    const float* eps     = (const float*)d_in[1];
    const float* c       = (const float*)d_in[2];
    const float* z_tilde = (const float*)d_in[3];
    const float* W_rr    = (const float*)d_in[4];
    const float* W_zr    = (const float*)d_in[5];
    const float* W_cr    = (const float*)d_in[6];
    const float* W_epsr  = (const float*)d_in[7];
    const float* W_rz    = (const float*)d_in[8];
    const float* W_rc    = (const float*)d_in[9];
    const float* b       = (const float*)d_in[10];
    float* out = (float*)d_out;

    k_rz  <<<(NZ / 4) * SPL_A, 256>>>(x, b, W_rz);
    k_big <<<N, 256>>>(W_rr, W_zr, W_cr, W_epsr, x, eps, c, b, out);
    k_tail<<<NZ + NC, 512>>>(W_rz, W_rc, z_tilde, out);
}

// round 14
// speedup vs baseline: 1.3238x; 1.0347x over previous
#include <cuda_runtime.h>
#include <math.h>

#define N   8192
#define NZ  256
#define NC  128
#define DT_ 0.1f

// k_rz: z = W_rz @ r, 8-way column split, 4 rows per block -> 512 blocks
#define SPL_A 8
#define CHA4  (N / 4 / SPL_A)          // 256 float4 per column chunk

// Scratch (__device__ globals)
__device__ float g_r[N];
__device__ float g_zpart[SPL_A][NZ];
__device__ float g_rn[N];

// Fast tanh: 1 - 2/(exp(2x)+1). MUFU.EX2 + MUFU.RCP path, no branches.
__inline__ __device__ float ftanh(float x) {
    float e = __expf(2.0f * x);
    return 1.0f - __fdividef(2.0f, e + 1.0f);
}

__inline__ __device__ float dot4(float4 a, float4 b) {
    return a.x * b.x + a.y * b.y + a.z * b.z + a.w * b.w;
}

// Block reduce, up to 16 warps. Valid in thread 0.
__inline__ __device__ float block_reduce_w(float v, int nwarps) {
    __shared__ float sm[16];
    const int lane = threadIdx.x & 31;
    const int wid  = threadIdx.x >> 5;
    #pragma unroll
    for (int o = 16; o; o >>= 1) v += __shfl_down_sync(0xffffffffu, v, o);
    if (lane == 0) sm[wid] = v;
    __syncthreads();
    if (wid == 0) {
        v = (lane < nwarps) ? sm[lane] : 0.f;
        #pragma unroll
        for (int o = 8; o; o >>= 1) v += __shfl_down_sync(0xffffffffu, v, o);
    }
    return v;
}

// 4-wide block reduce, 8 warps (256 threads). Valid in thread 0.
__inline__ __device__ float4 block_reduce4(float4 v) {
    __shared__ float4 sm4[8];
    const int lane = threadIdx.x & 31;
    const int wid  = threadIdx.x >> 5;
    #pragma unroll
    for (int o = 16; o; o >>= 1) {
        v.x += __shfl_down_sync(0xffffffffu, v.x, o);
        v.y += __shfl_down_sync(0xffffffffu, v.y, o);
        v.z += __shfl_down_sync(0xffffffffu, v.z, o);
        v.w += __shfl_down_sync(0xffffffffu, v.w, o);
    }
    if (lane == 0) sm4[wid] = v;
    __syncthreads();
    if (wid == 0) {
        v = (lane < 8) ? sm4[lane] : make_float4(0.f, 0.f, 0.f, 0.f);
        #pragma unroll
        for (int o = 4; o; o >>= 1) {
            v.x += __shfl_down_sync(0xffffffffu, v.x, o);
            v.y += __shfl_down_sync(0xffffffffu, v.y, o);
            v.z += __shfl_down_sync(0xffffffffu, v.z, o);
            v.w += __shfl_down_sync(0xffffffffu, v.w, o);
        }
    }
    return v;
}

// ---------------------------------------------------------------------------
// Kernel 1: r = tanh(x+b) for split-owned chunks (row-group 0 persists g_r)
// + split-K partials of z = W_rz @ r for 4 rows/block.
// Grid: 64 row-groups * 8 splits = 512 blocks, 256 threads (1 float4/thread).
// ---------------------------------------------------------------------------
__global__ void __launch_bounds__(256) k_rz(
    const float* __restrict__ x, const float* __restrict__ b,
    const float* __restrict__ W_rz)
{
    const int s    = blockIdx.x & (SPL_A - 1);
    const int rg   = blockIdx.x >> 3;
    const int row0 = rg * 4;
    const int c4   = s * CHA4 + threadIdx.x;

    float4 xv = ((const float4*)x)[c4];
    float4 bv = ((const float4*)b)[c4];

    const float4* w0 = (const float4*)(W_rz + (size_t)(row0 + 0) * N);
    const float4* w1 = (const float4*)(W_rz + (size_t)(row0 + 1) * N);
    const float4* w2 = (const float4*)(W_rz + (size_t)(row0 + 2) * N);
    const float4* w3 = (const float4*)(W_rz + (size_t)(row0 + 3) * N);
    float4 a0 = __ldcs(&w0[c4]);
    float4 a1 = __ldcs(&w1[c4]);
    float4 a2 = __ldcs(&w2[c4]);
    float4 a3 = __ldcs(&w3[c4]);

    float4 r0;
    r0.x = ftanh(xv.x + bv.x); r0.y = ftanh(xv.y + bv.y);
    r0.z = ftanh(xv.z + bv.z); r0.w = ftanh(xv.w + bv.w);
    if (rg == 0) ((float4*)g_r)[c4] = r0;

    float4 acc = make_float4(dot4(a0, r0), dot4(a1, r0),
                             dot4(a2, r0), dot4(a3, r0));
    acc = block_reduce4(acc);
    if (threadIdx.x == 0) {
        g_zpart[s][row0 + 0] = acc.x;
        g_zpart[s][row0 + 1] = acc.y;
        g_zpart[s][row0 + 2] = acc.z;
        g_zpart[s][row0 + 3] = acc.w;
    }
}

// ---------------------------------------------------------------------------
// Kernel 2: fused row update (R9 structure, 8x LDG.128 front-batched).
// PDL: prefetch all k_rz-INDEPENDENT data (W_rr row, side-matrix rows,
// eps, c) before cudaGridDependencySynchronize(); touch g_r / g_zpart after.
// Grid: 8192 blocks, 256 threads.
// ---------------------------------------------------------------------------
__global__ void __launch_bounds__(256) k_big(
    const float* __restrict__ W_rr, const float* __restrict__ W_zr,
    const float* __restrict__ W_cr, const float* __restrict__ W_epsr,
    const float* __restrict__ x,    const float* __restrict__ eps,
    const float* __restrict__ c,    const float* __restrict__ b,
    float* __restrict__ out)
{
    const int row = blockIdx.x;
    const int t   = threadIdx.x;

    const float4* __restrict__ w = (const float4*)(W_rr + (size_t)row * N);
    const float4* __restrict__ v = (const float4*)g_r;

    // ---- independent prefetch (overlaps k_rz under PDL) ----
    float4 wv[8];
    #pragma unroll
    for (int i = 0; i < 8; i++) wv[i] = __ldcs(&w[t + i * 256]);

    float4 sidew = make_float4(0.f, 0.f, 0.f, 0.f);   // side-matrix weights
    float4 sidev = make_float4(0.f, 0.f, 0.f, 0.f);   // eps / c (independent)
    if (t < 64) {
        sidew = __ldcs(((const float4*)(W_epsr + (size_t)row * NZ)) + t);
        sidev = ((const float4*)eps)[t];
    } else if (t < 128) {
        sidew = __ldcs(((const float4*)(W_zr + (size_t)row * NZ)) + (t - 64));
    } else if (t < 160) {
        sidew = __ldcs(((const float4*)(W_cr + (size_t)row * NC)) + (t - 128));
        sidev = ((const float4*)c)[t - 128];
    }

    // ---- wait for k_rz's g_r / g_zpart ----
    cudaGridDependencySynchronize();

    float a0 = 0.f, a1 = 0.f, a2 = 0.f, a3 = 0.f;
    #pragma unroll
    for (int i = 0; i < 8; i++) {
        float d = dot4(wv[i], v[t + i * 256]);   // g_r: L1-hit after first block
        if ((i & 3) == 0) a0 += d;
        else if ((i & 3) == 1) a1 += d;
        else if ((i & 3) == 2) a2 += d;
        else a3 += d;
    }
    float acc = (a0 + a1) + (a2 + a3);

    if (t < 64) {                               // W_epsr row · eps
        acc += dot4(sidew, sidev);
    } else if (t < 128) {                       // W_zr row · z (fixed split order)
        const int k = t - 64;
        float4 q = ((const float4*)g_zpart[0])[k];
        #pragma unroll
        for (int s = 1; s < SPL_A; s++) {
            float4 p = ((const float4*)g_zpart[s])[k];
            q.x += p.x; q.y += p.y; q.z += p.z; q.w += p.w;
        }
        acc += dot4(sidew, q);
    } else if (t < 160) {                       // W_cr row · c
        acc += dot4(sidew, sidev);
    }

    acc = block_reduce_w(acc, 8);
    if (t == 0) {
        float xv = x[row];
        float xn = xv + DT_ * (acc - xv);
        out[row] = xn;
        float rn = ftanh(xn + b[row]);
        out[N + row] = rn;
        g_rn[row] = rn;
    }
}

// ---------------------------------------------------------------------------
// Kernel 3: z_new / c_new / eps_new. One block per output row, 512 threads.
// PDL: prefetch W row (independent of k_big) before grid-sync; read g_rn after.
// ---------------------------------------------------------------------------
__global__ void __launch_bounds__(512) k_tail(
    const float* __restrict__ W_rz, const float* __restrict__ W_rc,
    const float* __restrict__ z_tilde, float* __restrict__ out)
{
    const int idx = blockIdx.x;     // 0..383
    const float* __restrict__ Wrow = (idx < NZ)
        ? (W_rz + (size_t)idx * N)
        : (W_rc + (size_t)(idx - NZ) * N);
    const float4* __restrict__ w = (const float4*)Wrow;
    const float4* __restrict__ v = (const float4*)g_rn;
    const int base = threadIdx.x * 4;

    // ---- independent prefetch (overlaps k_big's drain under PDL) ----
    float4 w0 = __ldcs(&w[base + 0]), w1 = __ldcs(&w[base + 1]);
    float4 w2 = __ldcs(&w[base + 2]), w3 = __ldcs(&w[base + 3]);

    // ---- wait for k_big's g_rn ----
    cudaGridDependencySynchronize();

    float4 v0 = v[base + 0], v1 = v[base + 1];
    float4 v2 = v[base + 2], v3 = v[base + 3];

    float acc = (dot4(w0, v0) + dot4(w1, v1)) + (dot4(w2, v2) + dot4(w3, v3));
    acc = block_reduce_w(acc, 16);
    if (threadIdx.x == 0) {
        if (idx < NZ) {
            out[2 * N + idx] = acc;                          // z_new
            out[2 * N + NZ + NC + idx] = acc - z_tilde[idx]; // eps_new
        } else {
            out[2 * N + NZ + (idx - NZ)] = acc;              // c_new
        }
    }
}

extern "C" void kernel_launch(void* const* d_in, const int* in_sizes, int n_in,
                              void* d_out, int out_size) {
    // metadata order: x, eps, c, z_tilde, W_rr, W_zr, W_cr, W_epsr, W_rz, W_rc, b
    const float* x       = (const float*)d_in[0];
    const float* eps     = (const float*)d_in[1];
    const float* c       = (const float*)d_in[2];
    const float* z_tilde = (const float*)d_in[3];
    const float* W_rr    = (const float*)d_in[4];
    const float* W_zr    = (const float*)d_in[5];
    const float* W_cr    = (const float*)d_in[6];
    const float* W_epsr  = (const float*)d_in[7];
    const float* W_rz    = (const float*)d_in[8];
    const float* W_rc    = (const float*)d_in[9];
    const float* b       = (const float*)d_in[10];
    float* out = (float*)d_out;

    k_rz<<<(NZ / 4) * SPL_A, 256>>>(x, b, W_rz);

    // k_big with PDL (fallback to a plain launch if unsupported; the device
    // grid-sync then degenerates to a no-op under normal stream serialization)
    {
        cudaLaunchConfig_t cfg = {};
        cfg.gridDim  = dim3(N);
        cfg.blockDim = dim3(256);
        cfg.dynamicSmemBytes = 0;
        cfg.stream = 0;
        cudaLaunchAttribute at[1];
        at[0].id = cudaLaunchAttributeProgrammaticStreamSerialization;
        at[0].val.programmaticStreamSerializationAllowed = 1;
        cfg.attrs = at; cfg.numAttrs = 1;
        cudaError_t e = cudaLaunchKernelEx(&cfg, k_big, W_rr, W_zr, W_cr,
                                           W_epsr, x, eps, c, b, out);
        if (e != cudaSuccess) {
            (void)cudaGetLastError();   // clear sticky error
            k_big<<<N, 256>>>(W_rr, W_zr, W_cr, W_epsr, x, eps, c, b, out);
        }
    }

    // k_tail with PDL (same fallback)
    {
        cudaLaunchConfig_t cfg = {};
        cfg.gridDim  = dim3(NZ + NC);
        cfg.blockDim = dim3(512);
        cfg.dynamicSmemBytes = 0;
        cfg.stream = 0;
        cudaLaunchAttribute at[1];
        at[0].id = cudaLaunchAttributeProgrammaticStreamSerialization;
        at[0].val.programmaticStreamSerializationAllowed = 1;
        cfg.attrs = at; cfg.numAttrs = 1;
        cudaError_t e = cudaLaunchKernelEx(&cfg, k_tail, W_rz, W_rc, z_tilde, out);
        if (e != cudaSuccess) {
            (void)cudaGetLastError();   // clear sticky error
            k_tail<<<NZ + NC, 512>>>(W_rz, W_rc, z_tilde, out);
        }
    }
}